// round 12
// baseline (speedup 1.0000x reference)
#include <cuda_runtime.h>
#include <cuda_fp16.h>

// Problem constants
#define T_  1024
#define H_  2048
#define I_  768
#define E_  32
#define K_  4
#define NA  (T_*K_)

#define KC  32
#define RS  80        // f16 SMEM row stride (32 fp16 + pad)
#define RRS 144       // raw fp32 SMEM row stride (32 fp32 + pad) — conflict-free, 16-aligned
#define WSCALE 1024.0f
#define WINV   (1.0f/1024.0f)
#define NPERS 296

// SMEM map (per CTA)
#define F16S     25600
#define RAWS     (192*RRS)            // 27648
#define OFF_RAW0 (2*F16S)             // 51200
#define OFF_RAW1 (OFF_RAW0 + RAWS)    // 78848
#define OFF_A2   (OFF_RAW1 + RAWS)    // 106496
#define OFF_META (OFF_A2 + 5120)      // 111616
#define MOE_SMEM (OFF_META + 512)     // 112128

// ---------------- portable PTX helpers ----------------
__device__ __forceinline__ unsigned smem_u32(const void* p) {
    unsigned a;
    asm("{ .reg .u64 t; cvta.to.shared.u64 t, %1; cvt.u32.u64 %0, t; }" : "=r"(a) : "l"(p));
    return a;
}
__device__ __forceinline__ void ldm4(unsigned* d, unsigned a) {
    asm volatile("ldmatrix.sync.aligned.m8n8.x4.shared.b16 {%0,%1,%2,%3}, [%4];"
        : "=r"(d[0]), "=r"(d[1]), "=r"(d[2]), "=r"(d[3]) : "r"(a));
}
__device__ __forceinline__ void mma4(float* c, const unsigned* a, const unsigned* b) {
    asm volatile("mma.sync.aligned.m16n8k16.row.col.f32.f16.f16.f32 "
        "{%0,%1,%2,%3},{%4,%5,%6,%7},{%8,%9},{%0,%1,%2,%3};"
        : "+f"(c[0]), "+f"(c[1]), "+f"(c[2]), "+f"(c[3])
        : "r"(a[0]), "r"(a[1]), "r"(a[2]), "r"(a[3]), "r"(b[0]), "r"(b[1]));
}
__device__ __forceinline__ void cpa16(unsigned saddr, const void* g) {
    asm volatile("cp.async.cg.shared.global [%0], [%1], 16;" :: "r"(saddr), "l"(g));
}
#define CP_COMMIT() asm volatile("cp.async.commit_group;")
#define CP_WAIT1()  asm volatile("cp.async.wait_group 1;")
#define CP_WAIT0()  asm volatile("cp.async.wait_group 0;")

__device__ __forceinline__ uint4 cvtA8(float4 a, float4 b) {
    float va[8] = {a.x, a.y, a.z, a.w, b.x, b.y, b.z, b.w};
    unsigned w[4];
#pragma unroll
    for (int j = 0; j < 4; j++) {
        __half2 h = __float22half2_rn(make_float2(va[2*j], va[2*j+1]));
        w[j] = *reinterpret_cast<unsigned*>(&h);
    }
    return make_uint4(w[0], w[1], w[2], w[3]);
}
__device__ __forceinline__ void cvtB8(float4 a, float4 b, uint4& hi, uint4& lo) {
    float va[8] = {a.x, a.y, a.z, a.w, b.x, b.y, b.z, b.w};
    unsigned hw[4], lw[4];
#pragma unroll
    for (int j = 0; j < 4; j++) {
        float2 f = make_float2(va[2*j] * WSCALE, va[2*j+1] * WSCALE);
        __half2 h = __float22half2_rn(f);
        float2 hf = __half22float2(h);
        __half2 l = __float22half2_rn(make_float2(f.x - hf.x, f.y - hf.y));
        hw[j] = *reinterpret_cast<unsigned*>(&h);
        lw[j] = *reinterpret_cast<unsigned*>(&l);
    }
    hi = make_uint4(hw[0], hw[1], hw[2], hw[3]);
    lo = make_uint4(lw[0], lw[1], lw[2], lw[3]);
}

// ---- device scratch ----
__device__ int   g_counts[E_];
__device__ int   g_offsets[E_];
__device__ int   g_perm[NA];
__device__ int   g_nrt;
__device__ int   g_rt_e[160];
__device__ int   g_rt_r0[160];
__device__ int   g_rt_full[160];
__device__ int   g_ready[160];
__device__ int   g_tick;
__device__ __align__(16) __half g_h[(size_t)NA * I_];
__device__ __align__(16) float  g_yp[(size_t)NA * H_];

// ---------------- routing: warp-private histograms ----------------
__global__ void k_route(const int* __restrict__ ids) {
    __shared__ int cntW[32][33];
    __shared__ int baseW[32][32];
    __shared__ int curW[32][32];
    __shared__ int offs[E_];
    int tid = threadIdx.x;       // 1024
    int w = tid >> 5, l = tid & 31;
    cntW[w][l] = 0; curW[w][l] = 0;
    if (tid < 160) g_ready[tid] = 0;
    __syncthreads();
    int myid[4];
#pragma unroll
    for (int j = 0; j < 4; j++) {
        int i = w*128 + j*32 + l;
        myid[j] = ids[i];
        atomicAdd(&cntW[w][myid[j]], 1);
    }
    __syncthreads();
    // per-(warp,expert) exclusive prefix over warps; warp 0 records totals
    {
        int e = l, s = 0, myb = 0;
        for (int w2 = 0; w2 < 32; w2++) {
            if (w2 == w) myb = s;
            s += cntW[w2][e];
        }
        baseW[w][e] = myb;
        if (w == 0) g_counts[e] = s;
    }
    __syncthreads();
    if (tid == 0) {
        int acc = 0, n = 0;
        for (int e = 0; e < E_; e++) {
            offs[e] = acc; g_offsets[e] = acc;
            int c = g_counts[e];
            for (int r0 = 0; r0 < c; r0 += 64) {
                g_rt_e[n] = e; g_rt_r0[n] = r0;
                g_rt_full[n] = (c - r0 > 32) ? 1 : 0;
                n++;
            }
            acc += c;
        }
        g_nrt = n;
        g_tick = 0;
    }
    __syncthreads();
#pragma unroll
    for (int j = 0; j < 4; j++) {
        int e = myid[j];
        int p = atomicAdd(&curW[w][e], 1);
        g_perm[offs[e] + baseW[w][e] + p] = w*128 + j*32 + l;
    }
}

// ---------------- fused persistent MoE kernel ----------------
// f16 stage layout (gateup): A 0, Bg_h 5120, Bg_l 10240, Bu_h 15360, Bu_l 20480
// f16 stage layout (down):   B_h 5120, B_l 15360 (A lives in the 3-deep ring)
// raw stage layout (gateup): x +0, wg +9216, wu +18432 (64 rows x RRS each)
// raw stage layout (down):   wd rows 0..127 at +row*RRS
#define HST2 144

__global__ void __launch_bounds__(256, 2) k_moe(
    const float* __restrict__ x,
    const float* __restrict__ Wg,
    const float* __restrict__ Wu,
    const float* __restrict__ Wd,
    const float* __restrict__ ew)
{
    extern __shared__ char smem[];
    unsigned sb = smem_u32(smem);
    int tid = threadIdx.x;
    int wid = tid >> 5, l = tid & 31;
    int wm = wid >> 2, wn = wid & 3;     // wm=0 warps are one per SMSP
    int ar = tid >> 2, ac = (tid & 3) * 8;
    int bR1 = (tid + 256) >> 2;

    int* meta = (int*)(smem + OFF_META);
    int* sT   = meta + 64;
    const int nrt = g_nrt;
    const int ngu = nrt * 12;
    const int ntot = ngu + nrt * 16;
    const unsigned rawb[2] = { sb + OFF_RAW0, sb + OFF_RAW1 };
    const unsigned ringb[3] = { sb, sb + F16S, sb + OFF_A2 };

    for (;;) {
        __syncthreads();
        if (tid == 0) *sT = atomicAdd(&g_tick, 1);
        __syncthreads();
        int t = *sT;
        if (t >= ntot) return;

        if (t < ngu) {
            // ================= gate+up tile: (64|32) x 64 =================
            int rt   = t / 12;
            int col0 = (t - rt*12) * 64;
            int e    = g_rt_e[rt];
            int row0 = g_rt_r0[rt];
            int cnt  = g_counts[e];
            int off  = g_offsets[e];
            bool act = g_rt_full[rt] || (wm == 0);

            if (tid < 64) {
                int r = row0 + tid;
                meta[tid] = g_perm[off + ((r < cnt) ? r : (cnt - 1))] >> 2;
            }
            __syncthreads();

            const float* wg = Wg + (size_t)e * I_ * H_ + (size_t)col0 * H_;
            const float* wu = Wu + (size_t)e * I_ * H_ + (size_t)col0 * H_;

            float cg[2][2][4], cu[2][2][4];
#pragma unroll
            for (int mt = 0; mt < 2; mt++)
#pragma unroll
                for (int nt = 0; nt < 2; nt++)
#pragma unroll
                    for (int j = 0; j < 4; j++) { cg[mt][nt][j] = 0.f; cu[mt][nt][j] = 0.f; }

            unsigned roff = (unsigned)(ar*RRS + ac*4);
            size_t xrow = (size_t)meta[ar] * H_;

            // prologue: async-load chunks 0,1
#pragma unroll
            for (int pk = 0; pk < 2; pk++) {
                unsigned rb = rawb[pk];
                int k0 = pk * KC;
                const float* p = x + xrow + k0 + ac;
                cpa16(rb + roff,      p);     cpa16(rb + roff + 16,      p + 4);
                p = wg + (size_t)ar * H_ + k0 + ac;
                cpa16(rb + 9216 + roff,  p);  cpa16(rb + 9216 + roff + 16,  p + 4);
                p = wu + (size_t)ar * H_ + k0 + ac;
                cpa16(rb + 18432 + roff, p);  cpa16(rb + 18432 + roff + 16, p + 4);
                CP_COMMIT();
            }
            CP_WAIT1();
            __syncthreads();
            // convert chunk 0 -> F0
            {
                char* rp = smem + OFF_RAW0;
                char* fp = smem;
                float4 v0 = *(float4*)(rp + ar*RRS + ac*4), v1 = *(float4*)(rp + ar*RRS + ac*4 + 16);
                *(uint4*)(fp + 0 + ar*RS + ac*2) = cvtA8(v0, v1);
                uint4 hv, lv;
                v0 = *(float4*)(rp + 9216 + ar*RRS + ac*4); v1 = *(float4*)(rp + 9216 + ar*RRS + ac*4 + 16);
                cvtB8(v0, v1, hv, lv);
                *(uint4*)(fp + 5120  + ar*RS + ac*2) = hv;
                *(uint4*)(fp + 10240 + ar*RS + ac*2) = lv;
                v0 = *(float4*)(rp + 18432 + ar*RRS + ac*4); v1 = *(float4*)(rp + 18432 + ar*RRS + ac*4 + 16);
                cvtB8(v0, v1, hv, lv);
                *(uint4*)(fp + 15360 + ar*RS + ac*2) = hv;
                *(uint4*)(fp + 20480 + ar*RS + ac*2) = lv;
            }
            __syncthreads();

            const int NK = H_ / KC;   // 64
            for (int k = 0; k < NK; k++) {
                int s = k & 1;
                if (k + 2 < NK) {
                    unsigned rb = rawb[s];
                    int k0 = (k + 2) * KC;
                    const float* p = x + xrow + k0 + ac;
                    cpa16(rb + roff,      p);     cpa16(rb + roff + 16,      p + 4);
                    p = wg + (size_t)ar * H_ + k0 + ac;
                    cpa16(rb + 9216 + roff,  p);  cpa16(rb + 9216 + roff + 16,  p + 4);
                    p = wu + (size_t)ar * H_ + k0 + ac;
                    cpa16(rb + 18432 + roff, p);  cpa16(rb + 18432 + roff + 16, p + 4);
                    CP_COMMIT();
                }

                unsigned stb = sb + s * F16S;
                if (act) {
#pragma unroll
                    for (int kk = 0; kk < 2; kk++) {
                        unsigned ah[2][4];
#pragma unroll
                        for (int mt = 0; mt < 2; mt++) {
                            unsigned arow = (unsigned)(wm*32 + mt*16 + (l & 15)) * RS;
                            unsigned ak   = (unsigned)(kk*16 + ((l >> 4) << 3)) * 2;
                            ldm4(ah[mt], stb + 0 + arow + ak);
                        }
                        unsigned bro = (unsigned)(wn*16 + ((l >> 4) & 1)*8 + (l & 7)) * RS
                                     + (unsigned)(kk*16 + ((l >> 3) & 1)*8) * 2;
                        unsigned bh[4], bl[4];
                        ldm4(bh, stb + 5120  + bro);
                        ldm4(bl, stb + 10240 + bro);
#pragma unroll
                        for (int mt = 0; mt < 2; mt++) {
                            mma4(cg[mt][0], ah[mt], bh);   mma4(cg[mt][1], ah[mt], bh+2);
                            mma4(cg[mt][0], ah[mt], bl);   mma4(cg[mt][1], ah[mt], bl+2);
                        }
                        ldm4(bh, stb + 15360 + bro);
                        ldm4(bl, stb + 20480 + bro);
#pragma unroll
                        for (int mt = 0; mt < 2; mt++) {
                            mma4(cu[mt][0], ah[mt], bh);   mma4(cu[mt][1], ah[mt], bh+2);
                            mma4(cu[mt][0], ah[mt], bl);   mma4(cu[mt][1], ah[mt], bl+2);
                        }
                    }
                }

                if (k + 1 < NK) {
                    if (k + 2 < NK) CP_WAIT1(); else CP_WAIT0();
                    char* rp = smem + ((s ^ 1) ? OFF_RAW1 : OFF_RAW0);
                    char* fp = smem + (s ^ 1) * F16S;
                    float4 v0 = *(float4*)(rp + ar*RRS + ac*4), v1 = *(float4*)(rp + ar*RRS + ac*4 + 16);
                    *(uint4*)(fp + 0 + ar*RS + ac*2) = cvtA8(v0, v1);
                    uint4 hv, lv;
                    v0 = *(float4*)(rp + 9216 + ar*RRS + ac*4); v1 = *(float4*)(rp + 9216 + ar*RRS + ac*4 + 16);
                    cvtB8(v0, v1, hv, lv);
                    *(uint4*)(fp + 5120  + ar*RS + ac*2) = hv;
                    *(uint4*)(fp + 10240 + ar*RS + ac*2) = lv;
                    v0 = *(float4*)(rp + 18432 + ar*RRS + ac*4); v1 = *(float4*)(rp + 18432 + ar*RRS + ac*4 + 16);
                    cvtB8(v0, v1, hv, lv);
                    *(uint4*)(fp + 15360 + ar*RS + ac*2) = hv;
                    *(uint4*)(fp + 20480 + ar*RS + ac*2) = lv;
                }
                __syncthreads();
            }

            // epilogue: h = silu(g/1024)*(u/1024) -> fp16, staged, coalesced store
            char* sh = smem;
            if (act) {
#pragma unroll
                for (int mt = 0; mt < 2; mt++)
#pragma unroll
                    for (int nt = 0; nt < 2; nt++)
#pragma unroll
                        for (int half = 0; half < 2; half++) {
                            int rr = wm*32 + mt*16 + (l >> 2) + half*8;
                            int cc = wn*16 + nt*8 + (l & 3)*2;
                            float g0 = cg[mt][nt][2*half]   * WINV, g1 = cg[mt][nt][2*half+1] * WINV;
                            float u0 = cu[mt][nt][2*half]   * WINV, u1 = cu[mt][nt][2*half+1] * WINV;
                            float h0 = (g0 / (1.f + __expf(-g0))) * u0;
                            float h1 = (g1 / (1.f + __expf(-g1))) * u1;
                            __half2 hb = __float22half2_rn(make_float2(h0, h1));
                            *(unsigned*)(sh + rr*HST2 + cc*2) = *reinterpret_cast<unsigned*>(&hb);
                        }
            }
            __syncthreads();
#pragma unroll
            for (int j = 0; j < 2; j++) {
                int u = tid + 256*j;
                int r = u >> 3, c8 = u & 7;
                if (row0 + r < cnt) {
                    size_t gidx = (size_t)(off + row0 + r) * I_ + col0 + c8*8;
                    *(uint4*)&g_h[gidx] = *(uint4*)(sh + r*HST2 + c8*16);
                }
            }
            __syncthreads();
            if (tid == 0) {
                __threadfence();
                atomicAdd(&g_ready[rt], 1);
            }
        } else {
            // ================= down tile: (64|32) x 128 =================
            int td   = t - ngu;
            int rt   = td / 16;
            int col0 = (td - rt*16) * 128;
            int e    = g_rt_e[rt];
            int row0 = g_rt_r0[rt];
            int cnt  = g_counts[e];
            int off  = g_offsets[e];
            bool act = g_rt_full[rt] || (wm == 0);

            if (tid == 0) {
                while (((volatile int*)g_ready)[rt] < 12) __nanosleep(64);
            }
            if (tid < 64) {
                int r = row0 + tid;
                meta[tid] = (r < cnt) ? g_perm[off + r] : -1;
            }
            __syncthreads();
            __threadfence();

            const float* wd = Wd + (size_t)e * H_ * I_ + (size_t)col0 * I_;

            float cd[2][4][4];
#pragma unroll
            for (int mt = 0; mt < 2; mt++)
#pragma unroll
                for (int nt = 0; nt < 4; nt++)
#pragma unroll
                    for (int j = 0; j < 4; j++) cd[mt][nt][j] = 0.f;

            int rrA = row0 + ar;
            size_t gA = (size_t)(off + ((rrA < cnt) ? rrA : (cnt - 1))) * I_;
            unsigned roff  = (unsigned)(ar*RRS + ac*4);
            unsigned roff1 = (unsigned)(bR1*RRS + ac*4);
            unsigned aoff  = (unsigned)(ar*RS + ac*2);

            // prologue: async-load chunks 0,1 (wd raw + A f16 ring)
#pragma unroll
            for (int pk = 0; pk < 2; pk++) {
                unsigned rb = rawb[pk];
                int k0 = pk * KC;
                const float* p = wd + (size_t)ar * I_ + k0 + ac;
                cpa16(rb + roff,  p);  cpa16(rb + roff + 16,  p + 4);
                p = wd + (size_t)bR1 * I_ + k0 + ac;
                cpa16(rb + roff1, p);  cpa16(rb + roff1 + 16, p + 4);
                cpa16(ringb[pk] + aoff, &g_h[gA + k0 + ac]);
                CP_COMMIT();
            }
            CP_WAIT1();
            __syncthreads();
            // convert chunk 0 B -> F0
            {
                char* rp = smem + OFF_RAW0;
                char* fp = smem;
                uint4 hv, lv;
                float4 v0 = *(float4*)(rp + ar*RRS + ac*4),  v1 = *(float4*)(rp + ar*RRS + ac*4 + 16);
                cvtB8(v0, v1, hv, lv);
                *(uint4*)(fp + 5120  + ar*RS + ac*2) = hv;
                *(uint4*)(fp + 15360 + ar*RS + ac*2) = lv;
                v0 = *(float4*)(rp + bR1*RRS + ac*4); v1 = *(float4*)(rp + bR1*RRS + ac*4 + 16);
                cvtB8(v0, v1, hv, lv);
                *(uint4*)(fp + 5120  + bR1*RS + ac*2) = hv;
                *(uint4*)(fp + 15360 + bR1*RS + ac*2) = lv;
            }
            __syncthreads();

            const int NK = I_ / KC;   // 24
            for (int k = 0; k < NK; k++) {
                int s = k & 1;
                if (k + 2 < NK) {
                    unsigned rb = rawb[s];
                    int k0 = (k + 2) * KC;
                    const float* p = wd + (size_t)ar * I_ + k0 + ac;
                    cpa16(rb + roff,  p);  cpa16(rb + roff + 16,  p + 4);
                    p = wd + (size_t)bR1 * I_ + k0 + ac;
                    cpa16(rb + roff1, p);  cpa16(rb + roff1 + 16, p + 4);
                    cpa16(ringb[(k + 2) % 3] + aoff, &g_h[gA + k0 + ac]);
                    CP_COMMIT();
                }

                unsigned stb = sb + s * F16S;
                unsigned abase = ringb[k % 3];
                if (act) {
#pragma unroll
                    for (int kk = 0; kk < 2; kk++) {
                        unsigned ah[2][4];
#pragma unroll
                        for (int mt = 0; mt < 2; mt++) {
                            unsigned arow = (unsigned)(wm*32 + mt*16 + (l & 15)) * RS;
                            unsigned ak   = (unsigned)(kk*16 + ((l >> 4) << 3)) * 2;
                            ldm4(ah[mt], abase + arow + ak);
                        }
#pragma unroll
                        for (int nt16 = 0; nt16 < 2; nt16++) {
                            unsigned bro = (unsigned)(wn*32 + nt16*16 + ((l >> 4) & 1)*8 + (l & 7)) * RS
                                         + (unsigned)(kk*16 + ((l >> 3) & 1)*8) * 2;
                            unsigned bh[4], bl[4];
                            ldm4(bh, stb + 5120  + bro);
                            ldm4(bl, stb + 15360 + bro);
#pragma unroll
                            for (int mt = 0; mt < 2; mt++) {
                                mma4(cd[mt][2*nt16],   ah[mt], bh);   mma4(cd[mt][2*nt16+1], ah[mt], bh+2);
                                mma4(cd[mt][2*nt16],   ah[mt], bl);   mma4(cd[mt][2*nt16+1], ah[mt], bl+2);
                            }
                        }
                    }
                }

                if (k + 1 < NK) {
                    if (k + 2 < NK) CP_WAIT1(); else CP_WAIT0();
                    char* rp = smem + ((s ^ 1) ? OFF_RAW1 : OFF_RAW0);
                    char* fp = smem + (s ^ 1) * F16S;
                    uint4 hv, lv;
                    float4 v0 = *(float4*)(rp + ar*RRS + ac*4),  v1 = *(float4*)(rp + ar*RRS + ac*4 + 16);
                    cvtB8(v0, v1, hv, lv);
                    *(uint4*)(fp + 5120  + ar*RS + ac*2) = hv;
                    *(uint4*)(fp + 15360 + ar*RS + ac*2) = lv;
                    v0 = *(float4*)(rp + bR1*RRS + ac*4); v1 = *(float4*)(rp + bR1*RRS + ac*4 + 16);
                    cvtB8(v0, v1, hv, lv);
                    *(uint4*)(fp + 5120  + bR1*RS + ac*2) = hv;
                    *(uint4*)(fp + 15360 + bR1*RS + ac*2) = lv;
                }
                __syncthreads();
            }

            // epilogue
            if (act) {
#pragma unroll
                for (int mt = 0; mt < 2; mt++)
#pragma unroll
                    for (int half = 0; half < 2; half++) {
                        int rr = wm*32 + mt*16 + (l >> 2) + half*8;
                        int pv = meta[rr];
                        if (pv >= 0) {
                            float w = ew[pv] * WINV;
                            size_t base = (size_t)pv * H_ + col0 + wn*32 + (l & 3)*2;
#pragma unroll
                            for (int nt = 0; nt < 4; nt++) {
                                float2 v = make_float2(w * cd[mt][nt][2*half], w * cd[mt][nt][2*half+1]);
                                *(float2*)(&g_yp[base + nt*8]) = v;
                            }
                        }
                    }
            }
        }
    }
}

// ---------------- combine ----------------
__global__ void k_combine(float* __restrict__ y) {
    int i = blockIdx.x * blockDim.x + threadIdx.x;
    if (i < T_ * H_ / 4) {
        int t  = i / (H_ / 4);
        int h4 = i - t * (H_ / 4);
        const float4* p = (const float4*)(&g_yp[(size_t)(t * K_) * H_]) + h4;
        float4 a = p[0];
        float4 b = p[H_ / 4];
        float4 c = p[2 * (H_ / 4)];
        float4 d = p[3 * (H_ / 4)];
        float4 o;
        o.x = a.x + b.x + c.x + d.x;
        o.y = a.y + b.y + c.y + d.y;
        o.z = a.z + b.z + c.z + d.z;
        o.w = a.w + b.w + c.w + d.w;
        ((float4*)y)[i] = o;
    }
}

// ---------------- launch ----------------
extern "C" void kernel_launch(void* const* d_in, const int* in_sizes, int n_in,
                              void* d_out, int out_size)
{
    const float* x   = (const float*)d_in[0];
    const float* Wg  = (const float*)d_in[1];
    const float* Wu  = (const float*)d_in[2];
    const float* Wd  = (const float*)d_in[3];
    const int*   ids = (const int*)d_in[4];
    const float* ew  = (const float*)d_in[5];
    float*       y   = (float*)d_out;

    cudaFuncSetAttribute(k_moe, cudaFuncAttributeMaxDynamicSharedMemorySize, MOE_SMEM);

    k_route<<<1, 1024>>>(ids);
    k_moe<<<NPERS, 256, MOE_SMEM>>>(x, Wg, Wu, Wd, ew);
    k_combine<<<(T_ * H_ / 4 + 255) / 256, 256>>>(y);
}

// round 13
// speedup vs baseline: 1.2799x; 1.2799x over previous
#include <cuda_runtime.h>
#include <cuda_fp16.h>

// Problem constants
#define T_  1024
#define H_  2048
#define I_  768
#define E_  32
#define K_  4
#define NA  (T_*K_)   // 4096 assignment rows

#define KC  32
#define RS  80        // SMEM row stride bytes (32 fp16 + 16B pad) — conflict-free ldmatrix
#define WSCALE 1024.0f
#define WINV   (1.0f/1024.0f)
#define NPERS 296     // persistent CTAs (2/SM x 148)

// ---------------- portable PTX helpers ----------------
__device__ __forceinline__ unsigned smem_u32(const void* p) {
    unsigned a;
    asm("{ .reg .u64 t; cvta.to.shared.u64 t, %1; cvt.u32.u64 %0, t; }" : "=r"(a) : "l"(p));
    return a;
}

__device__ __forceinline__ void ldm4(unsigned* d, unsigned a) {
    asm volatile("ldmatrix.sync.aligned.m8n8.x4.shared.b16 {%0,%1,%2,%3}, [%4];"
        : "=r"(d[0]), "=r"(d[1]), "=r"(d[2]), "=r"(d[3]) : "r"(a));
}

__device__ __forceinline__ void mma4(float* c, const unsigned* a, const unsigned* b) {
    asm volatile("mma.sync.aligned.m16n8k16.row.col.f32.f16.f16.f32 "
        "{%0,%1,%2,%3},{%4,%5,%6,%7},{%8,%9},{%0,%1,%2,%3};"
        : "+f"(c[0]), "+f"(c[1]), "+f"(c[2]), "+f"(c[3])
        : "r"(a[0]), "r"(a[1]), "r"(a[2]), "r"(a[3]), "r"(b[0]), "r"(b[1]));
}

// L2-direct async copy (bypass L1) — used for g_h reads in the down phase
__device__ __forceinline__ void cpasync16cg(unsigned saddr, const void* g) {
    asm volatile("cp.async.cg.shared.global [%0], [%1], 16;" :: "r"(saddr), "l"(g));
}
#define CP_COMMIT() asm volatile("cp.async.commit_group;")
#define CP_WAIT0()  asm volatile("cp.async.wait_group 0;")

// 8 fp32 -> 8 plain fp16 (activations)
__device__ __forceinline__ uint4 cvtA8(float4 a, float4 b) {
    float va[8] = {a.x, a.y, a.z, a.w, b.x, b.y, b.z, b.w};
    unsigned w[4];
#pragma unroll
    for (int j = 0; j < 4; j++) {
        __half2 h = __float22half2_rn(make_float2(va[2*j], va[2*j+1]));
        w[j] = *reinterpret_cast<unsigned*>(&h);
    }
    return make_uint4(w[0], w[1], w[2], w[3]);
}

// 8 fp32 weights -> scaled (x1024) fp16 hi + lo
__device__ __forceinline__ void cvtB8(float4 a, float4 b, uint4& hi, uint4& lo) {
    float va[8] = {a.x, a.y, a.z, a.w, b.x, b.y, b.z, b.w};
    unsigned hw[4], lw[4];
#pragma unroll
    for (int j = 0; j < 4; j++) {
        float2 f = make_float2(va[2*j] * WSCALE, va[2*j+1] * WSCALE);
        __half2 h = __float22half2_rn(f);
        float2 hf = __half22float2(h);
        __half2 l = __float22half2_rn(make_float2(f.x - hf.x, f.y - hf.y));
        hw[j] = *reinterpret_cast<unsigned*>(&h);
        lw[j] = *reinterpret_cast<unsigned*>(&l);
    }
    hi = make_uint4(hw[0], hw[1], hw[2], hw[3]);
    lo = make_uint4(lw[0], lw[1], lw[2], lw[3]);
}

// 8 fp32 weights -> scaled fp16 hi only (down GEMM, 1-term)
__device__ __forceinline__ uint4 cvtB8h(float4 a, float4 b) {
    float va[8] = {a.x, a.y, a.z, a.w, b.x, b.y, b.z, b.w};
    unsigned hw[4];
#pragma unroll
    for (int j = 0; j < 4; j++) {
        __half2 h = __float22half2_rn(make_float2(va[2*j] * WSCALE, va[2*j+1] * WSCALE));
        hw[j] = *reinterpret_cast<unsigned*>(&h);
    }
    return make_uint4(hw[0], hw[1], hw[2], hw[3]);
}

// ---- device scratch ----
__device__ int   g_counts[E_];
__device__ int   g_offsets[E_];
__device__ int   g_perm[NA];
__device__ int   g_nrt;
__device__ int   g_rt_e[160];
__device__ int   g_rt_r0[160];
__device__ int   g_rt_full[160];   // 1 = 64-row tile, 0 = 32-row remainder tile
__device__ int   g_ready[160];
__device__ int   g_tick;
__device__ __align__(16) __half g_h[(size_t)NA * I_];
__device__ __align__(16) float  g_yp[(size_t)NA * H_];

// ---------------- routing + tile list ----------------
__global__ void k_route(const int* __restrict__ ids) {
    __shared__ int cnt[E_], offs[E_], cur[E_];
    int tid = threadIdx.x;   // 1024
    if (tid < E_) { cnt[tid] = 0; cur[tid] = 0; }
    if (tid < 160) g_ready[tid] = 0;
    __syncthreads();
    for (int i = tid; i < NA; i += 1024) atomicAdd(&cnt[ids[i]], 1);
    __syncthreads();
    if (tid == 0) {
        int acc = 0, n = 0;
        for (int e = 0; e < E_; e++) {
            offs[e] = acc; g_offsets[e] = acc; g_counts[e] = cnt[e]; acc += cnt[e];
            for (int r0 = 0; r0 < cnt[e]; r0 += 64) {
                int rem = cnt[e] - r0;
                g_rt_e[n] = e; g_rt_r0[n] = r0;
                g_rt_full[n] = (rem > 32) ? 1 : 0;
                n++;
            }
        }
        g_nrt = n;
        g_tick = 0;
    }
    __syncthreads();
    for (int i = tid; i < NA; i += 1024) {
        int e = ids[i];
        int p = atomicAdd(&cur[e], 1);
        g_perm[offs[e] + p] = i;
    }
}

// ---------------- fused persistent MoE kernel ----------------
// SMEM: two 25600-B stages + 512 B tile metadata + tick slot.
// gateup stage: A 0 (5120), Bg_h 5120, Bg_l 10240, Bu_h 15360, Bu_l 20480
// down   stage: A 0 (5120), B_h 5120 (10240)   [1-term: no B_l]
#define STAGE 25600
#define MOE_SMEM (2*STAGE + 1024)
#define HST2 144   // gateup epilogue staging row stride

__global__ void __launch_bounds__(256, 2) k_moe(
    const float* __restrict__ x,
    const float* __restrict__ Wg,
    const float* __restrict__ Wu,
    const float* __restrict__ Wd,
    const float* __restrict__ ew)
{
    extern __shared__ char smem[];
    unsigned sb = smem_u32(smem);
    int tid = threadIdx.x;
    int wid = tid >> 5, l = tid & 31;
    // wm=0 warps are wid 0..3 — one per SMSP, so 32-row tiles keep all
    // sub-partitions' tensor units busy while wm=1 warps idle.
    int wm = wid >> 2, wn = wid & 3;
    int ar = tid >> 2, ac = (tid & 3) * 8;
    int bR1 = (tid + 256) >> 2;           // second B slot row (down phase)

    int* meta = (int*)(smem + 2*STAGE);   // [0..63] toks/pvS, [64] tick
    int* sT   = meta + 64;
    const int nrt = g_nrt;
    const int ngu = nrt * 12;
    const int ntot = ngu + nrt * 16;

    for (;;) {
        __syncthreads();
        if (tid == 0) *sT = atomicAdd(&g_tick, 1);
        __syncthreads();
        int t = *sT;
        if (t >= ntot) return;

        if (t < ngu) {
            // ================= gate+up tile: (64|32) x 64 =================
            int rt   = t / 12;
            int col0 = (t - rt*12) * 64;
            int e    = g_rt_e[rt];
            int row0 = g_rt_r0[rt];
            int cnt  = g_counts[e];
            int off  = g_offsets[e];
            bool act = g_rt_full[rt] || (wm == 0);   // warp participates in MMA

            if (tid < 64) {
                int r = row0 + tid;
                meta[tid] = g_perm[off + ((r < cnt) ? r : (cnt - 1))] >> 2;
            }
            __syncthreads();

            const float* wg = Wg + (size_t)e * I_ * H_ + (size_t)col0 * H_;
            const float* wu = Wu + (size_t)e * I_ * H_ + (size_t)col0 * H_;

            float cg[2][2][4], cu[2][2][4];
#pragma unroll
            for (int mt = 0; mt < 2; mt++)
#pragma unroll
                for (int nt = 0; nt < 2; nt++)
#pragma unroll
                    for (int j = 0; j < 4; j++) { cg[mt][nt][j] = 0.f; cu[mt][nt][j] = 0.f; }

            size_t xrow = (size_t)meta[ar] * H_;

            // prologue: chunk 0 -> stage 0
            {
                char* st = smem;
                const float* p = x + xrow + ac;
                *(uint4*)(st + 0 + ar*RS + ac*2) = cvtA8(*(const float4*)p, *(const float4*)(p + 4));
                uint4 hv, lv;
                const float* pg = wg + (size_t)ar * H_ + ac;
                cvtB8(*(const float4*)pg, *(const float4*)(pg + 4), hv, lv);
                *(uint4*)(st + 5120  + ar*RS + ac*2) = hv;
                *(uint4*)(st + 10240 + ar*RS + ac*2) = lv;
                const float* pu = wu + (size_t)ar * H_ + ac;
                cvtB8(*(const float4*)pu, *(const float4*)(pu + 4), hv, lv);
                *(uint4*)(st + 15360 + ar*RS + ac*2) = hv;
                *(uint4*)(st + 20480 + ar*RS + ac*2) = lv;
            }
            __syncthreads();

            const int NK = H_ / KC;   // 64
            for (int k = 0; k < NK; k++) {
                int s = k & 1;
                bool pf = (k + 1 < NK);
                float4 pa0, pa1, pg0, pg1, pu0, pu1;
                if (pf) {
                    int k0 = (k + 1) * KC;
                    const float* p;
                    p = x + xrow + k0 + ac;             pa0 = *(const float4*)p; pa1 = *(const float4*)(p + 4);
                    p = wg + (size_t)ar * H_ + k0 + ac; pg0 = *(const float4*)p; pg1 = *(const float4*)(p + 4);
                    p = wu + (size_t)ar * H_ + k0 + ac; pu0 = *(const float4*)p; pu1 = *(const float4*)(p + 4);
                }

                unsigned stb = sb + s * STAGE;
                if (act) {
#pragma unroll
                    for (int kk = 0; kk < 2; kk++) {
                        unsigned ah[2][4];
#pragma unroll
                        for (int mt = 0; mt < 2; mt++) {
                            unsigned arow = (unsigned)(wm*32 + mt*16 + (l & 15)) * RS;
                            unsigned ak   = (unsigned)(kk*16 + ((l >> 4) << 3)) * 2;
                            ldm4(ah[mt], stb + 0 + arow + ak);
                        }
                        unsigned bro = (unsigned)(wn*16 + ((l >> 4) & 1)*8 + (l & 7)) * RS
                                     + (unsigned)(kk*16 + ((l >> 3) & 1)*8) * 2;
                        unsigned bh[4], bl[4];
                        ldm4(bh, stb + 5120  + bro);
                        ldm4(bl, stb + 10240 + bro);
#pragma unroll
                        for (int mt = 0; mt < 2; mt++) {
                            mma4(cg[mt][0], ah[mt], bh);   mma4(cg[mt][1], ah[mt], bh+2);
                            mma4(cg[mt][0], ah[mt], bl);   mma4(cg[mt][1], ah[mt], bl+2);
                        }
                        ldm4(bh, stb + 15360 + bro);
                        ldm4(bl, stb + 20480 + bro);
#pragma unroll
                        for (int mt = 0; mt < 2; mt++) {
                            mma4(cu[mt][0], ah[mt], bh);   mma4(cu[mt][1], ah[mt], bh+2);
                            mma4(cu[mt][0], ah[mt], bl);   mma4(cu[mt][1], ah[mt], bl+2);
                        }
                    }
                }

                if (pf) {
                    char* st = smem + (s ^ 1) * STAGE;
                    *(uint4*)(st + 0 + ar*RS + ac*2) = cvtA8(pa0, pa1);
                    uint4 hv, lv;
                    cvtB8(pg0, pg1, hv, lv);
                    *(uint4*)(st + 5120  + ar*RS + ac*2) = hv;
                    *(uint4*)(st + 10240 + ar*RS + ac*2) = lv;
                    cvtB8(pu0, pu1, hv, lv);
                    *(uint4*)(st + 15360 + ar*RS + ac*2) = hv;
                    *(uint4*)(st + 20480 + ar*RS + ac*2) = lv;
                }
                __syncthreads();
            }

            // epilogue: h = silu(g/1024)*(u/1024) -> fp16, staged, coalesced store
            char* sh = smem;   // 64 x HST2 = 9216 B
            if (act) {
#pragma unroll
                for (int mt = 0; mt < 2; mt++)
#pragma unroll
                    for (int nt = 0; nt < 2; nt++)
#pragma unroll
                        for (int half = 0; half < 2; half++) {
                            int rr = wm*32 + mt*16 + (l >> 2) + half*8;
                            int cc = wn*16 + nt*8 + (l & 3)*2;
                            float g0 = cg[mt][nt][2*half]   * WINV, g1 = cg[mt][nt][2*half+1] * WINV;
                            float u0 = cu[mt][nt][2*half]   * WINV, u1 = cu[mt][nt][2*half+1] * WINV;
                            float h0 = (g0 / (1.f + __expf(-g0))) * u0;
                            float h1 = (g1 / (1.f + __expf(-g1))) * u1;
                            __half2 hb = __float22half2_rn(make_float2(h0, h1));
                            *(unsigned*)(sh + rr*HST2 + cc*2) = *reinterpret_cast<unsigned*>(&hb);
                        }
            }
            __syncthreads();
#pragma unroll
            for (int j = 0; j < 2; j++) {
                int u = tid + 256*j;       // 512 slots: 64 rows x 8 uint4
                int r = u >> 3, c8 = u & 7;
                if (row0 + r < cnt) {
                    size_t gidx = (size_t)(off + row0 + r) * I_ + col0 + c8*8;
                    *(uint4*)&g_h[gidx] = *(uint4*)(sh + r*HST2 + c8*16);
                }
            }
            __syncthreads();
            if (tid == 0) {
                __threadfence();
                atomicAdd(&g_ready[rt], 1);
            }
        } else {
            // ================= down tile: (64|32) x 128, 1-term =================
            int td   = t - ngu;
            int rt   = td / 16;
            int col0 = (td - rt*16) * 128;
            int e    = g_rt_e[rt];
            int row0 = g_rt_r0[rt];
            int cnt  = g_counts[e];
            int off  = g_offsets[e];
            bool act = g_rt_full[rt] || (wm == 0);

            if (tid == 0) {
                while (((volatile int*)g_ready)[rt] < 12) __nanosleep(64);
            }
            if (tid < 64) {
                int r = row0 + tid;
                meta[tid] = (r < cnt) ? g_perm[off + r] : -1;
            }
            __syncthreads();
            __threadfence();   // acquire: g_h reads below must see producer stores

            const float* wd = Wd + (size_t)e * H_ * I_ + (size_t)col0 * I_;

            float cd[2][4][4];
#pragma unroll
            for (int mt = 0; mt < 2; mt++)
#pragma unroll
                for (int nt = 0; nt < 4; nt++)
#pragma unroll
                    for (int j = 0; j < 4; j++) cd[mt][nt][j] = 0.f;

            int rrA = row0 + ar;
            size_t gA = (size_t)(off + ((rrA < cnt) ? rrA : (cnt - 1))) * I_;

            // prologue: chunk 0 -> stage 0
            {
                char* st = smem;
                cpasync16cg(sb + 0 + ar*RS + ac*2, &g_h[gA + ac]);
                CP_COMMIT();
                const float* p;
                p = wd + (size_t)ar * I_ + ac;
                *(uint4*)(st + 5120 + ar*RS + ac*2)  = cvtB8h(*(const float4*)p, *(const float4*)(p + 4));
                p = wd + (size_t)bR1 * I_ + ac;
                *(uint4*)(st + 5120 + bR1*RS + ac*2) = cvtB8h(*(const float4*)p, *(const float4*)(p + 4));
                CP_WAIT0();
            }
            __syncthreads();

            const int NK = I_ / KC;   // 24
            for (int k = 0; k < NK; k++) {
                int s = k & 1;
                bool pf = (k + 1 < NK);
                float4 pb0, pb1, pb2, pb3;
                if (pf) {
                    int k0 = (k + 1) * KC;
                    cpasync16cg(sb + (s ^ 1) * STAGE + 0 + ar*RS + ac*2, &g_h[gA + k0 + ac]);
                    CP_COMMIT();
                    const float* p;
                    p = wd + (size_t)ar * I_ + k0 + ac;  pb0 = *(const float4*)p; pb1 = *(const float4*)(p + 4);
                    p = wd + (size_t)bR1 * I_ + k0 + ac; pb2 = *(const float4*)p; pb3 = *(const float4*)(p + 4);
                }

                unsigned stb = sb + s * STAGE;
                if (act) {
#pragma unroll
                    for (int kk = 0; kk < 2; kk++) {
                        unsigned ah[2][4];
#pragma unroll
                        for (int mt = 0; mt < 2; mt++) {
                            unsigned arow = (unsigned)(wm*32 + mt*16 + (l & 15)) * RS;
                            unsigned ak   = (unsigned)(kk*16 + ((l >> 4) << 3)) * 2;
                            ldm4(ah[mt], stb + 0 + arow + ak);
                        }
#pragma unroll
                        for (int nt16 = 0; nt16 < 2; nt16++) {
                            unsigned bro = (unsigned)(wn*32 + nt16*16 + ((l >> 4) & 1)*8 + (l & 7)) * RS
                                         + (unsigned)(kk*16 + ((l >> 3) & 1)*8) * 2;
                            unsigned bh[4];
                            ldm4(bh, stb + 5120 + bro);
#pragma unroll
                            for (int mt = 0; mt < 2; mt++) {
                                mma4(cd[mt][2*nt16],   ah[mt], bh);   mma4(cd[mt][2*nt16+1], ah[mt], bh+2);
                            }
                        }
                    }
                }

                if (pf) {
                    char* st = smem + (s ^ 1) * STAGE;
                    *(uint4*)(st + 5120 + ar*RS + ac*2)  = cvtB8h(pb0, pb1);
                    *(uint4*)(st + 5120 + bR1*RS + ac*2) = cvtB8h(pb2, pb3);
                    CP_WAIT0();
                }
                __syncthreads();
            }

            // epilogue: scale by router weight / 1024, scatter rows of g_yp
            if (act) {
#pragma unroll
                for (int mt = 0; mt < 2; mt++)
#pragma unroll
                    for (int half = 0; half < 2; half++) {
                        int rr = wm*32 + mt*16 + (l >> 2) + half*8;
                        int pv = meta[rr];
                        if (pv >= 0) {
                            float w = ew[pv] * WINV;
                            size_t base = (size_t)pv * H_ + col0 + wn*32 + (l & 3)*2;
#pragma unroll
                            for (int nt = 0; nt < 4; nt++) {
                                float2 v = make_float2(w * cd[mt][nt][2*half], w * cd[mt][nt][2*half+1]);
                                *(float2*)(&g_yp[base + nt*8]) = v;
                            }
                        }
                    }
            }
        }
    }
}

// ---------------- combine ----------------
__global__ void k_combine(float* __restrict__ y) {
    int i = blockIdx.x * blockDim.x + threadIdx.x;
    if (i < T_ * H_ / 4) {
        int t  = i / (H_ / 4);
        int h4 = i - t * (H_ / 4);
        const float4* p = (const float4*)(&g_yp[(size_t)(t * K_) * H_]) + h4;
        float4 a = p[0];
        float4 b = p[H_ / 4];
        float4 c = p[2 * (H_ / 4)];
        float4 d = p[3 * (H_ / 4)];
        float4 o;
        o.x = a.x + b.x + c.x + d.x;
        o.y = a.y + b.y + c.y + d.y;
        o.z = a.z + b.z + c.z + d.z;
        o.w = a.w + b.w + c.w + d.w;
        ((float4*)y)[i] = o;
    }
}

// ---------------- launch ----------------
extern "C" void kernel_launch(void* const* d_in, const int* in_sizes, int n_in,
                              void* d_out, int out_size)
{
    const float* x   = (const float*)d_in[0];
    const float* Wg  = (const float*)d_in[1];
    const float* Wu  = (const float*)d_in[2];
    const float* Wd  = (const float*)d_in[3];
    const int*   ids = (const int*)d_in[4];
    const float* ew  = (const float*)d_in[5];
    float*       y   = (float*)d_out;

    cudaFuncSetAttribute(k_moe, cudaFuncAttributeMaxDynamicSharedMemorySize, MOE_SMEM);

    k_route<<<1, 1024>>>(ids);
    k_moe<<<NPERS, 256, MOE_SMEM>>>(x, Wg, Wu, Wd, ew);
    k_combine<<<(T_ * H_ / 4 + 255) / 256, 256>>>(y);
}

// round 14
// speedup vs baseline: 1.4515x; 1.1340x over previous
#include <cuda_runtime.h>
#include <cuda_fp16.h>

// Problem constants
#define T_  1024
#define H_  2048
#define I_  768
#define E_  32
#define K_  4
#define NA  (T_*K_)   // 4096 assignment rows

#define KC  32
#define RS  80        // SMEM row stride bytes (32 fp16 + 16B pad) — conflict-free ldmatrix
#define WSCALE 1024.0f
#define WINV   (1.0f/1024.0f)
#define NPERS 296     // persistent CTAs (2/SM x 148)

// ---------------- portable PTX helpers ----------------
__device__ __forceinline__ unsigned smem_u32(const void* p) {
    unsigned a;
    asm("{ .reg .u64 t; cvta.to.shared.u64 t, %1; cvt.u32.u64 %0, t; }" : "=r"(a) : "l"(p));
    return a;
}

__device__ __forceinline__ void ldm4(unsigned* d, unsigned a) {
    asm volatile("ldmatrix.sync.aligned.m8n8.x4.shared.b16 {%0,%1,%2,%3}, [%4];"
        : "=r"(d[0]), "=r"(d[1]), "=r"(d[2]), "=r"(d[3]) : "r"(a));
}

__device__ __forceinline__ void mma4(float* c, const unsigned* a, const unsigned* b) {
    asm volatile("mma.sync.aligned.m16n8k16.row.col.f32.f16.f16.f32 "
        "{%0,%1,%2,%3},{%4,%5,%6,%7},{%8,%9},{%0,%1,%2,%3};"
        : "+f"(c[0]), "+f"(c[1]), "+f"(c[2]), "+f"(c[3])
        : "r"(a[0]), "r"(a[1]), "r"(a[2]), "r"(a[3]), "r"(b[0]), "r"(b[1]));
}

// L2-direct async copy (bypass L1) — used for g_h reads in the down phase
__device__ __forceinline__ void cpasync16cg(unsigned saddr, const void* g) {
    asm volatile("cp.async.cg.shared.global [%0], [%1], 16;" :: "r"(saddr), "l"(g));
}
#define CP_COMMIT() asm volatile("cp.async.commit_group;")
#define CP_WAIT0()  asm volatile("cp.async.wait_group 0;")

// 8 fp32 -> 8 plain fp16 (activations)
__device__ __forceinline__ uint4 cvtA8(float4 a, float4 b) {
    float va[8] = {a.x, a.y, a.z, a.w, b.x, b.y, b.z, b.w};
    unsigned w[4];
#pragma unroll
    for (int j = 0; j < 4; j++) {
        __half2 h = __float22half2_rn(make_float2(va[2*j], va[2*j+1]));
        w[j] = *reinterpret_cast<unsigned*>(&h);
    }
    return make_uint4(w[0], w[1], w[2], w[3]);
}

// 8 fp32 weights -> scaled (x1024) fp16 hi only (1-term emulation)
__device__ __forceinline__ uint4 cvtB8h(float4 a, float4 b) {
    float va[8] = {a.x, a.y, a.z, a.w, b.x, b.y, b.z, b.w};
    unsigned hw[4];
#pragma unroll
    for (int j = 0; j < 4; j++) {
        __half2 h = __float22half2_rn(make_float2(va[2*j] * WSCALE, va[2*j+1] * WSCALE));
        hw[j] = *reinterpret_cast<unsigned*>(&h);
    }
    return make_uint4(hw[0], hw[1], hw[2], hw[3]);
}

// ---- device scratch ----
__device__ int   g_counts[E_];
__device__ int   g_offsets[E_];
__device__ int   g_perm[NA];
__device__ int   g_nrt;
__device__ int   g_rt_e[160];
__device__ int   g_rt_r0[160];
__device__ int   g_rt_full[160];   // 1 = 64-row tile, 0 = 32-row remainder tile
__device__ int   g_ready[160];
__device__ int   g_tick;
__device__ __align__(16) __half g_h[(size_t)NA * I_];
__device__ __align__(16) float  g_yp[(size_t)NA * H_];

// ---------------- routing + tile list ----------------
__global__ void k_route(const int* __restrict__ ids) {
    __shared__ int cnt[E_], offs[E_], cur[E_];
    int tid = threadIdx.x;   // 1024
    if (tid < E_) { cnt[tid] = 0; cur[tid] = 0; }
    if (tid < 160) g_ready[tid] = 0;
    __syncthreads();
    for (int i = tid; i < NA; i += 1024) atomicAdd(&cnt[ids[i]], 1);
    __syncthreads();
    if (tid == 0) {
        int acc = 0, n = 0;
        for (int e = 0; e < E_; e++) {
            offs[e] = acc; g_offsets[e] = acc; g_counts[e] = cnt[e]; acc += cnt[e];
            for (int r0 = 0; r0 < cnt[e]; r0 += 64) {
                int rem = cnt[e] - r0;
                g_rt_e[n] = e; g_rt_r0[n] = r0;
                g_rt_full[n] = (rem > 32) ? 1 : 0;
                n++;
            }
        }
        g_nrt = n;
        g_tick = 0;
    }
    __syncthreads();
    for (int i = tid; i < NA; i += 1024) {
        int e = ids[i];
        int p = atomicAdd(&cur[e], 1);
        g_perm[offs[e] + p] = i;
    }
}

// ---------------- fused persistent MoE kernel ----------------
// SMEM: two 15360-B stages + 512 B tile metadata.
// gateup stage: A 0 (5120), Bg_h 5120 (5120), Bu_h 10240 (5120)
// down   stage: A 0 (5120), B_h 5120 (10240)
#define STAGE 15360
#define MOE_SMEM (2*STAGE + 1024)
#define HST2 144   // gateup epilogue staging row stride

__global__ void __launch_bounds__(256, 2) k_moe(
    const float* __restrict__ x,
    const float* __restrict__ Wg,
    const float* __restrict__ Wu,
    const float* __restrict__ Wd,
    const float* __restrict__ ew)
{
    extern __shared__ char smem[];
    unsigned sb = smem_u32(smem);
    int tid = threadIdx.x;
    int wid = tid >> 5, l = tid & 31;
    // wm=0 warps are wid 0..3 — one per SMSP, so 32-row tiles keep all
    // sub-partitions' tensor units busy while wm=1 warps idle.
    int wm = wid >> 2, wn = wid & 3;
    int ar = tid >> 2, ac = (tid & 3) * 8;
    int bR1 = (tid + 256) >> 2;           // second B slot row (down phase)

    int* meta = (int*)(smem + 2*STAGE);   // [0..63] toks/pvS, [64] tick
    int* sT   = meta + 64;
    const int nrt = g_nrt;
    const int ngu = nrt * 12;
    const int ntot = ngu + nrt * 16;

    for (;;) {
        __syncthreads();
        if (tid == 0) *sT = atomicAdd(&g_tick, 1);
        __syncthreads();
        int t = *sT;
        if (t >= ntot) return;

        if (t < ngu) {
            // ================= gate+up tile: (64|32) x 64, 1-term =================
            int rt   = t / 12;
            int col0 = (t - rt*12) * 64;
            int e    = g_rt_e[rt];
            int row0 = g_rt_r0[rt];
            int cnt  = g_counts[e];
            int off  = g_offsets[e];
            bool act = g_rt_full[rt] || (wm == 0);   // warp participates in MMA

            if (tid < 64) {
                int r = row0 + tid;
                meta[tid] = g_perm[off + ((r < cnt) ? r : (cnt - 1))] >> 2;
            }
            __syncthreads();

            const float* wg = Wg + (size_t)e * I_ * H_ + (size_t)col0 * H_;
            const float* wu = Wu + (size_t)e * I_ * H_ + (size_t)col0 * H_;

            float cg[2][2][4], cu[2][2][4];
#pragma unroll
            for (int mt = 0; mt < 2; mt++)
#pragma unroll
                for (int nt = 0; nt < 2; nt++)
#pragma unroll
                    for (int j = 0; j < 4; j++) { cg[mt][nt][j] = 0.f; cu[mt][nt][j] = 0.f; }

            size_t xrow = (size_t)meta[ar] * H_;

            // prologue: chunk 0 -> stage 0
            {
                char* st = smem;
                const float* p = x + xrow + ac;
                *(uint4*)(st + 0 + ar*RS + ac*2) = cvtA8(*(const float4*)p, *(const float4*)(p + 4));
                p = wg + (size_t)ar * H_ + ac;
                *(uint4*)(st + 5120  + ar*RS + ac*2) = cvtB8h(*(const float4*)p, *(const float4*)(p + 4));
                p = wu + (size_t)ar * H_ + ac;
                *(uint4*)(st + 10240 + ar*RS + ac*2) = cvtB8h(*(const float4*)p, *(const float4*)(p + 4));
            }
            __syncthreads();

            const int NK = H_ / KC;   // 64
            for (int k = 0; k < NK; k++) {
                int s = k & 1;
                bool pf = (k + 1 < NK);
                float4 pa0, pa1, pg0, pg1, pu0, pu1;
                if (pf) {
                    int k0 = (k + 1) * KC;
                    const float* p;
                    p = x + xrow + k0 + ac;             pa0 = *(const float4*)p; pa1 = *(const float4*)(p + 4);
                    p = wg + (size_t)ar * H_ + k0 + ac; pg0 = *(const float4*)p; pg1 = *(const float4*)(p + 4);
                    p = wu + (size_t)ar * H_ + k0 + ac; pu0 = *(const float4*)p; pu1 = *(const float4*)(p + 4);
                }

                unsigned stb = sb + s * STAGE;
                if (act) {
#pragma unroll
                    for (int kk = 0; kk < 2; kk++) {
                        unsigned ah[2][4];
#pragma unroll
                        for (int mt = 0; mt < 2; mt++) {
                            unsigned arow = (unsigned)(wm*32 + mt*16 + (l & 15)) * RS;
                            unsigned ak   = (unsigned)(kk*16 + ((l >> 4) << 3)) * 2;
                            ldm4(ah[mt], stb + 0 + arow + ak);
                        }
                        unsigned bro = (unsigned)(wn*16 + ((l >> 4) & 1)*8 + (l & 7)) * RS
                                     + (unsigned)(kk*16 + ((l >> 3) & 1)*8) * 2;
                        unsigned bh[4];
                        ldm4(bh, stb + 5120 + bro);
#pragma unroll
                        for (int mt = 0; mt < 2; mt++) {
                            mma4(cg[mt][0], ah[mt], bh);   mma4(cg[mt][1], ah[mt], bh+2);
                        }
                        ldm4(bh, stb + 10240 + bro);
#pragma unroll
                        for (int mt = 0; mt < 2; mt++) {
                            mma4(cu[mt][0], ah[mt], bh);   mma4(cu[mt][1], ah[mt], bh+2);
                        }
                    }
                }

                if (pf) {
                    char* st = smem + (s ^ 1) * STAGE;
                    *(uint4*)(st + 0 + ar*RS + ac*2)     = cvtA8(pa0, pa1);
                    *(uint4*)(st + 5120  + ar*RS + ac*2) = cvtB8h(pg0, pg1);
                    *(uint4*)(st + 10240 + ar*RS + ac*2) = cvtB8h(pu0, pu1);
                }
                __syncthreads();
            }

            // epilogue: h = silu(g/1024)*(u/1024) -> fp16, staged, coalesced store
            char* sh = smem;   // 64 x HST2 = 9216 B
            if (act) {
#pragma unroll
                for (int mt = 0; mt < 2; mt++)
#pragma unroll
                    for (int nt = 0; nt < 2; nt++)
#pragma unroll
                        for (int half = 0; half < 2; half++) {
                            int rr = wm*32 + mt*16 + (l >> 2) + half*8;
                            int cc = wn*16 + nt*8 + (l & 3)*2;
                            float g0 = cg[mt][nt][2*half]   * WINV, g1 = cg[mt][nt][2*half+1] * WINV;
                            float u0 = cu[mt][nt][2*half]   * WINV, u1 = cu[mt][nt][2*half+1] * WINV;
                            float h0 = (g0 / (1.f + __expf(-g0))) * u0;
                            float h1 = (g1 / (1.f + __expf(-g1))) * u1;
                            __half2 hb = __float22half2_rn(make_float2(h0, h1));
                            *(unsigned*)(sh + rr*HST2 + cc*2) = *reinterpret_cast<unsigned*>(&hb);
                        }
            }
            __syncthreads();
#pragma unroll
            for (int j = 0; j < 2; j++) {
                int u = tid + 256*j;       // 512 slots: 64 rows x 8 uint4
                int r = u >> 3, c8 = u & 7;
                if (row0 + r < cnt) {
                    size_t gidx = (size_t)(off + row0 + r) * I_ + col0 + c8*8;
                    *(uint4*)&g_h[gidx] = *(uint4*)(sh + r*HST2 + c8*16);
                }
            }
            __syncthreads();
            if (tid == 0) {
                __threadfence();
                atomicAdd(&g_ready[rt], 1);
            }
        } else {
            // ================= down tile: (64|32) x 128, 1-term =================
            int td   = t - ngu;
            int rt   = td / 16;
            int col0 = (td - rt*16) * 128;
            int e    = g_rt_e[rt];
            int row0 = g_rt_r0[rt];
            int cnt  = g_counts[e];
            int off  = g_offsets[e];
            bool act = g_rt_full[rt] || (wm == 0);

            if (tid == 0) {
                while (((volatile int*)g_ready)[rt] < 12) __nanosleep(64);
            }
            if (tid < 64) {
                int r = row0 + tid;
                meta[tid] = (r < cnt) ? g_perm[off + r] : -1;
            }
            __syncthreads();
            __threadfence();   // acquire: g_h reads below must see producer stores

            const float* wd = Wd + (size_t)e * H_ * I_ + (size_t)col0 * I_;

            float cd[2][4][4];
#pragma unroll
            for (int mt = 0; mt < 2; mt++)
#pragma unroll
                for (int nt = 0; nt < 4; nt++)
#pragma unroll
                    for (int j = 0; j < 4; j++) cd[mt][nt][j] = 0.f;

            int rrA = row0 + ar;
            size_t gA = (size_t)(off + ((rrA < cnt) ? rrA : (cnt - 1))) * I_;

            // prologue: chunk 0 -> stage 0
            {
                char* st = smem;
                cpasync16cg(sb + 0 + ar*RS + ac*2, &g_h[gA + ac]);
                CP_COMMIT();
                const float* p;
                p = wd + (size_t)ar * I_ + ac;
                *(uint4*)(st + 5120 + ar*RS + ac*2)  = cvtB8h(*(const float4*)p, *(const float4*)(p + 4));
                p = wd + (size_t)bR1 * I_ + ac;
                *(uint4*)(st + 5120 + bR1*RS + ac*2) = cvtB8h(*(const float4*)p, *(const float4*)(p + 4));
                CP_WAIT0();
            }
            __syncthreads();

            const int NK = I_ / KC;   // 24
            for (int k = 0; k < NK; k++) {
                int s = k & 1;
                bool pf = (k + 1 < NK);
                float4 pb0, pb1, pb2, pb3;
                if (pf) {
                    int k0 = (k + 1) * KC;
                    cpasync16cg(sb + (s ^ 1) * STAGE + 0 + ar*RS + ac*2, &g_h[gA + k0 + ac]);
                    CP_COMMIT();
                    const float* p;
                    p = wd + (size_t)ar * I_ + k0 + ac;  pb0 = *(const float4*)p; pb1 = *(const float4*)(p + 4);
                    p = wd + (size_t)bR1 * I_ + k0 + ac; pb2 = *(const float4*)p; pb3 = *(const float4*)(p + 4);
                }

                unsigned stb = sb + s * STAGE;
                if (act) {
#pragma unroll
                    for (int kk = 0; kk < 2; kk++) {
                        unsigned ah[2][4];
#pragma unroll
                        for (int mt = 0; mt < 2; mt++) {
                            unsigned arow = (unsigned)(wm*32 + mt*16 + (l & 15)) * RS;
                            unsigned ak   = (unsigned)(kk*16 + ((l >> 4) << 3)) * 2;
                            ldm4(ah[mt], stb + 0 + arow + ak);
                        }
#pragma unroll
                        for (int nt16 = 0; nt16 < 2; nt16++) {
                            unsigned bro = (unsigned)(wn*32 + nt16*16 + ((l >> 4) & 1)*8 + (l & 7)) * RS
                                         + (unsigned)(kk*16 + ((l >> 3) & 1)*8) * 2;
                            unsigned bh[4];
                            ldm4(bh, stb + 5120 + bro);
#pragma unroll
                            for (int mt = 0; mt < 2; mt++) {
                                mma4(cd[mt][2*nt16],   ah[mt], bh);   mma4(cd[mt][2*nt16+1], ah[mt], bh+2);
                            }
                        }
                    }
                }

                if (pf) {
                    char* st = smem + (s ^ 1) * STAGE;
                    *(uint4*)(st + 5120 + ar*RS + ac*2)  = cvtB8h(pb0, pb1);
                    *(uint4*)(st + 5120 + bR1*RS + ac*2) = cvtB8h(pb2, pb3);
                    CP_WAIT0();
                }
                __syncthreads();
            }

            // epilogue: scale by router weight / 1024, scatter rows of g_yp
            if (act) {
#pragma unroll
                for (int mt = 0; mt < 2; mt++)
#pragma unroll
                    for (int half = 0; half < 2; half++) {
                        int rr = wm*32 + mt*16 + (l >> 2) + half*8;
                        int pv = meta[rr];
                        if (pv >= 0) {
                            float w = ew[pv] * WINV;
                            size_t base = (size_t)pv * H_ + col0 + wn*32 + (l & 3)*2;
#pragma unroll
                            for (int nt = 0; nt < 4; nt++) {
                                float2 v = make_float2(w * cd[mt][nt][2*half], w * cd[mt][nt][2*half+1]);
                                *(float2*)(&g_yp[base + nt*8]) = v;
                            }
                        }
                    }
            }
        }
    }
}

// ---------------- combine ----------------
__global__ void k_combine(float* __restrict__ y) {
    int i = blockIdx.x * blockDim.x + threadIdx.x;
    if (i < T_ * H_ / 4) {
        int t  = i / (H_ / 4);
        int h4 = i - t * (H_ / 4);
        const float4* p = (const float4*)(&g_yp[(size_t)(t * K_) * H_]) + h4;
        float4 a = p[0];
        float4 b = p[H_ / 4];
        float4 c = p[2 * (H_ / 4)];
        float4 d = p[3 * (H_ / 4)];
        float4 o;
        o.x = a.x + b.x + c.x + d.x;
        o.y = a.y + b.y + c.y + d.y;
        o.z = a.z + b.z + c.z + d.z;
        o.w = a.w + b.w + c.w + d.w;
        ((float4*)y)[i] = o;
    }
}

// ---------------- launch ----------------
extern "C" void kernel_launch(void* const* d_in, const int* in_sizes, int n_in,
                              void* d_out, int out_size)
{
    const float* x   = (const float*)d_in[0];
    const float* Wg  = (const float*)d_in[1];
    const float* Wu  = (const float*)d_in[2];
    const float* Wd  = (const float*)d_in[3];
    const int*   ids = (const int*)d_in[4];
    const float* ew  = (const float*)d_in[5];
    float*       y   = (float*)d_out;

    cudaFuncSetAttribute(k_moe, cudaFuncAttributeMaxDynamicSharedMemorySize, MOE_SMEM);

    k_route<<<1, 1024>>>(ids);
    k_moe<<<NPERS, 256, MOE_SMEM>>>(x, Wg, Wu, Wd, ew);
    k_combine<<<(T_ * H_ / 4 + 255) / 256, 256>>>(y);
}